// round 2
// baseline (speedup 1.0000x reference)
#include <cuda_runtime.h>
#include <math.h>

#define BATCH 2048
#define NQ    10
#define NGEN  4
#define DEPTH 6
#define PATCH 256
#define QOUT  1024
#define NCLS  10

// ---------------- scratch (device globals; no allocation) ----------------
__device__ __align__(256) float g_angles[BATCH * 2 * NQ];   // (B,20)
__device__ __align__(256) float g_qf[BATCH * QOUT];         // (B,1024)
__device__ __align__(256) float g_y1[BATCH * 128];
__device__ __align__(256) float g_y2[BATCH * 128];
__device__ __align__(16)  float g_bns1[128], g_bnh1[128], g_bns2[128], g_bnh2[128];

__device__ __forceinline__ float leaky(float x) { return x > 0.f ? x : 0.2f * x; }

// =====================================================================
// Embedding MLP: labels(2048x10) -> 32 -> 64 -> 20 angles (tanh * pi)
// One warp per row; h1/h2 staged in shared per warp.
// =====================================================================
__global__ void __launch_bounds__(256) embed_kernel(
    const float* __restrict__ lab,
    const float* __restrict__ ew1, const float* __restrict__ eb1,
    const float* __restrict__ ew2, const float* __restrict__ eb2,
    const float* __restrict__ ew3, const float* __restrict__ eb3)
{
    const int wip  = threadIdx.x >> 5;
    const int row  = blockIdx.x * 8 + wip;
    const unsigned lane = threadIdx.x & 31u;
    __shared__ float h1s[8][32];
    __shared__ float h2s[8][64];

    float lv[NCLS];
    const float* L = lab + row * NCLS;
#pragma unroll
    for (int c = 0; c < NCLS; ++c) lv[c] = L[c];

    // h1[lane]
    {
        float a = eb1[lane];
#pragma unroll
        for (int c = 0; c < NCLS; ++c) a = fmaf(lv[c], ew1[lane * NCLS + c], a);
        h1s[wip][lane] = leaky(a);
    }
    __syncwarp();
    // h2: two outputs per lane
#pragma unroll
    for (int j = 0; j < 2; ++j) {
        const int o = lane + 32 * j;
        float a = eb2[o];
#pragma unroll
        for (int i = 0; i < 32; ++i) a = fmaf(h1s[wip][i], ew2[o * 32 + i], a);
        h2s[wip][o] = leaky(a);
    }
    __syncwarp();
    if (lane < 2 * NQ) {
        float a = eb3[lane];
#pragma unroll
        for (int i = 0; i < 64; ++i) a = fmaf(h2s[wip][i], ew3[lane * 64 + i], a);
        g_angles[row * 2 * NQ + lane] = tanhf(a) * 3.14159265358979323846f;
    }
}

// =====================================================================
// Quantum circuit simulator: one warp per (batch, generator) circuit.
// State: 1024 complex amps; flat index i = reg*32 + lane.
// Qubit q occupies bit (9-q): q<=4 -> register bit (4-q), q>=5 -> lane bit (9-q).
// =====================================================================

// real-state RY (state known real: before any RZ)
template <int B>
__device__ __forceinline__ void ry_r(float (&re)[32], float c, float s, unsigned lane)
{
    if (B >= 5) {
        const int m = 1 << (B - 5);
#pragma unroll
        for (int r = 0; r < 32; ++r) {
            if (!(r & m)) {
                const float a0 = re[r], a1 = re[r | m];
                re[r]     = fmaf(-s, a1, c * a0);
                re[r | m] = fmaf( s, a0, c * a1);
            }
        }
    } else {
        const unsigned mk = 1u << B;
        const float t = (lane & mk) ? s : -s;
#pragma unroll
        for (int r = 0; r < 32; ++r) {
            const float p = __shfl_xor_sync(0xffffffffu, re[r], mk);
            re[r] = fmaf(t, p, c * re[r]);
        }
    }
}

// complex RY
template <int B>
__device__ __forceinline__ void ry_c(float (&re)[32], float (&im)[32], float c, float s, unsigned lane)
{
    if (B >= 5) {
        const int m = 1 << (B - 5);
#pragma unroll
        for (int r = 0; r < 32; ++r) {
            if (!(r & m)) {
                const float a0r = re[r], a1r = re[r | m];
                const float a0i = im[r], a1i = im[r | m];
                re[r]     = fmaf(-s, a1r, c * a0r);
                re[r | m] = fmaf( s, a0r, c * a1r);
                im[r]     = fmaf(-s, a1i, c * a0i);
                im[r | m] = fmaf( s, a0i, c * a1i);
            }
        }
    } else {
        const unsigned mk = 1u << B;
        const float t = (lane & mk) ? s : -s;
#pragma unroll
        for (int r = 0; r < 32; ++r) {
            const float pr = __shfl_xor_sync(0xffffffffu, re[r], mk);
            const float pi = __shfl_xor_sync(0xffffffffu, im[r], mk);
            re[r] = fmaf(t, pr, c * re[r]);
            im[r] = fmaf(t, pi, c * im[r]);
        }
    }
}

// complex RZ: amp *= e^{i*sigma*theta/2}, sigma=+1 if bit set else -1
template <int B>
__device__ __forceinline__ void rz_c(float (&re)[32], float (&im)[32], float c, float s, unsigned lane)
{
    if (B < 5) {
        const float ss = (lane & (1u << B)) ? s : -s;
#pragma unroll
        for (int r = 0; r < 32; ++r) {
            const float rr = re[r], ii = im[r];
            re[r] = fmaf(-ss, ii, c * rr);
            im[r] = fmaf( ss, rr, c * ii);
        }
    } else {
#pragma unroll
        for (int r = 0; r < 32; ++r) {
            const float ss = (r & (1 << (B - 5))) ? s : -s;
            const float rr = re[r], ii = im[r];
            re[r] = fmaf(-ss, ii, c * rr);
            im[r] = fmaf( ss, rr, c * ii);
        }
    }
}

__global__ void __launch_bounds__(256, 2) qsim_kernel(
    const float* __restrict__ noise, const float* __restrict__ qp)
{
    const int w = (blockIdx.x * 256 + threadIdx.x) >> 5;   // 0..8191
    const unsigned lane = threadIdx.x & 31u;
    const int b = w >> 2, g = w & 3;
    const float* nz = noise + b * NQ;
    const float* an = g_angles + b * 2 * NQ;
    const float* wp = qp + g * DEPTH * NQ;

    float re[32], im[32];
#pragma unroll
    for (int r = 0; r < 32; ++r) re[r] = 0.f;
    if (lane == 0) re[0] = 1.f;

    float c, s;
    // --- 10 noise RYs (real state) ---
#define RYN(q) { __sincosf(0.5f * nz[q], &s, &c); ry_r<9 - (q)>(re, c, s, lane); }
    RYN(0) RYN(1) RYN(2) RYN(3) RYN(4) RYN(5) RYN(6) RYN(7) RYN(8) RYN(9)
#undef RYN
    // --- 10 angle RYs (still real; RZs commuted to after) ---
#define RYA(q) { __sincosf(0.5f * an[q], &s, &c); ry_r<9 - (q)>(re, c, s, lane); }
    RYA(0) RYA(1) RYA(2) RYA(3) RYA(4) RYA(5) RYA(6) RYA(7) RYA(8) RYA(9)
#undef RYA

#pragma unroll
    for (int r = 0; r < 32; ++r) im[r] = 0.f;

    // --- 10 RZs (commute-reordered; exact) ---
#define RZA(q) { __sincosf(0.5f * an[NQ + (q)], &s, &c); rz_c<9 - (q)>(re, im, c, s, lane); }
    RZA(0) RZA(1) RZA(2) RZA(3) RZA(4) RZA(5) RZA(6) RZA(7) RZA(8) RZA(9)
#undef RZA

    // CZ chain sign parity decomposition:
    // sign(i) flips iff popc(i & (i>>1)) odd, i = (r<<5)|lane.
    const bool pA = (__popc(lane & (lane >> 1)) & 1) != 0;
    const bool pB = pA ^ (((lane >> 4) & 1u) != 0);

    // --- 6 variational layers ---
#pragma unroll 1
    for (int l = 0; l < DEPTH; ++l) {
        const float* wl = wp + l * NQ;
        float cc[NQ], sv[NQ];
#pragma unroll
        for (int q = 0; q < NQ; ++q) __sincosf(0.5f * wl[q], &sv[q], &cc[q]);
#define RYW(q) ry_c<9 - (q)>(re, im, cc[q], sv[q], lane);
        RYW(0) RYW(1) RYW(2) RYW(3) RYW(4) RYW(5) RYW(6) RYW(7) RYW(8) RYW(9)
#undef RYW
        // combined CZ(0,1)...CZ(8,9)
#pragma unroll
        for (int r = 0; r < 32; ++r) {
            const bool srg = ((__popc(r & (r >> 1)) & 1) != 0);
            const bool neg = ((r & 1) ? pB : pA) ^ srg;
            if (neg) { re[r] = -re[r]; im[r] = -im[r]; }
        }
    }

    // --- output: probs of first 256 amps (regs 0..7), / max ---
    float p[8];
    float mx = 0.f;
#pragma unroll
    for (int r = 0; r < 8; ++r) {
        p[r] = fmaf(re[r], re[r], im[r] * im[r]);
        mx = fmaxf(mx, p[r]);
    }
#pragma unroll
    for (int o = 16; o; o >>= 1) mx = fmaxf(mx, __shfl_xor_sync(0xffffffffu, mx, o));
    const float inv = 1.0f / mx;
    float* dst = g_qf + b * QOUT + g * PATCH;
#pragma unroll
    for (int r = 0; r < 8; ++r) dst[r * 32 + lane] = p[r] * inv;
}

// =====================================================================
// Post-MLP layer 1: y1 = leaky([qf | labels] @ pw1.T + pb1)   K=1034
// Block: 32 rows x 128 cols, 256 threads, 4x4 microtile.
// =====================================================================
__global__ void __launch_bounds__(256) gemm1_kernel(
    const float* __restrict__ lab, const float* __restrict__ W, const float* __restrict__ bias)
{
    __shared__ float xs[32][33];
    __shared__ float ws[32][128];
    __shared__ float labs[32][NCLS];
    const int rowBase = blockIdx.x * 32;
    const int tid = threadIdx.x;
    const int ty = tid >> 5, tx = tid & 31;

    float acc[4][4];
#pragma unroll
    for (int i = 0; i < 4; ++i)
#pragma unroll
        for (int j = 0; j < 4; ++j) acc[i][j] = 0.f;

    // FIX (R1): 320 elements > 256 threads -> strided load (was a coverage hole
    // leaving labs rows 25..31 uninitialized, poisoning BN stats downstream).
    for (int t = tid; t < 32 * NCLS; t += 256)
        labs[t / NCLS][t % NCLS] = lab[(rowBase + t / NCLS) * NCLS + t % NCLS];

    for (int kb = 0; kb < QOUT; kb += 32) {
        __syncthreads();
        {   // x tile: float4 along k
            const int row = tid >> 3;
            const int k4  = (tid & 7) * 4;
            const float4 v = *reinterpret_cast<const float4*>(&g_qf[(rowBase + row) * QOUT + kb + k4]);
            xs[k4 + 0][row] = v.x; xs[k4 + 1][row] = v.y;
            xs[k4 + 2][row] = v.z; xs[k4 + 3][row] = v.w;
        }
        {   // w tile: float2 (row length 1034 -> only 8B alignment guaranteed)
            const int col = tid >> 1;
            const int k0  = (tid & 1) * 16;
#pragma unroll
            for (int u = 0; u < 16; u += 2) {
                const float2 v = *reinterpret_cast<const float2*>(&W[col * 1034 + kb + k0 + u]);
                ws[k0 + u + 0][col] = v.x;
                ws[k0 + u + 1][col] = v.y;
            }
        }
        __syncthreads();
#pragma unroll
        for (int kk = 0; kk < 32; ++kk) {
            float a[4], bb[4];
#pragma unroll
            for (int i = 0; i < 4; ++i) a[i] = xs[kk][ty * 4 + i];
#pragma unroll
            for (int j = 0; j < 4; ++j) bb[j] = ws[kk][tx + 32 * j];
#pragma unroll
            for (int i = 0; i < 4; ++i)
#pragma unroll
                for (int j = 0; j < 4; ++j) acc[i][j] = fmaf(a[i], bb[j], acc[i][j]);
        }
    }

    // label tail (k = 1024..1033) + bias + leaky + store
#pragma unroll
    for (int j = 0; j < 4; ++j) {
        const int col = tx + 32 * j;
        float wt[NCLS];
#pragma unroll
        for (int cI = 0; cI < NCLS; ++cI) wt[cI] = W[col * 1034 + QOUT + cI];
        const float bcol = bias[col];
#pragma unroll
        for (int i = 0; i < 4; ++i) {
            const int row = ty * 4 + i;
            float v = acc[i][j] + bcol;
#pragma unroll
            for (int cI = 0; cI < NCLS; ++cI) v = fmaf(labs[row][cI], wt[cI], v);
            g_y1[(rowBase + row) * 128 + col] = leaky(v);
        }
    }
}

// =====================================================================
// BatchNorm stats: per-column mean/var over batch -> affine (scale, shift)
// =====================================================================
__global__ void __launch_bounds__(256) bnstats1_kernel(
    const float* __restrict__ gamma, const float* __restrict__ beta)
{
    const int c = blockIdx.x;
    float s1 = 0.f, s2 = 0.f;
    for (int i = threadIdx.x; i < BATCH; i += 256) {
        const float v = g_y1[i * 128 + c];
        s1 += v; s2 = fmaf(v, v, s2);
    }
    __shared__ float sh1[256], sh2[256];
    sh1[threadIdx.x] = s1; sh2[threadIdx.x] = s2;
    __syncthreads();
    for (int o = 128; o > 0; o >>= 1) {
        if (threadIdx.x < o) { sh1[threadIdx.x] += sh1[threadIdx.x + o]; sh2[threadIdx.x] += sh2[threadIdx.x + o]; }
        __syncthreads();
    }
    if (threadIdx.x == 0) {
        const float mu  = sh1[0] * (1.f / BATCH);
        const float var = sh2[0] * (1.f / BATCH) - mu * mu;
        const float rstd = rsqrtf(var + 1e-5f);
        const float sc = gamma[c] * rstd;
        g_bns1[c] = sc;
        g_bnh1[c] = beta[c] - mu * sc;
    }
}

__global__ void __launch_bounds__(256) bnstats2_kernel(
    const float* __restrict__ gamma, const float* __restrict__ beta)
{
    const int c = blockIdx.x;
    float s1 = 0.f, s2 = 0.f;
    for (int i = threadIdx.x; i < BATCH; i += 256) {
        const float v = g_y2[i * 128 + c];
        s1 += v; s2 = fmaf(v, v, s2);
    }
    __shared__ float sh1[256], sh2[256];
    sh1[threadIdx.x] = s1; sh2[threadIdx.x] = s2;
    __syncthreads();
    for (int o = 128; o > 0; o >>= 1) {
        if (threadIdx.x < o) { sh1[threadIdx.x] += sh1[threadIdx.x + o]; sh2[threadIdx.x] += sh2[threadIdx.x + o]; }
        __syncthreads();
    }
    if (threadIdx.x == 0) {
        const float mu  = sh1[0] * (1.f / BATCH);
        const float var = sh2[0] * (1.f / BATCH) - mu * mu;
        const float rstd = rsqrtf(var + 1e-5f);
        const float sc = gamma[c] * rstd;
        g_bns2[c] = sc;
        g_bnh2[c] = beta[c] - mu * sc;
    }
}

// =====================================================================
// Layer 2: y2 = leaky( BN1(y1) @ pw2.T + pb2 )    K=128
// =====================================================================
__global__ void __launch_bounds__(256) gemm2_kernel(
    const float* __restrict__ W, const float* __restrict__ bias)
{
    __shared__ float xs[32][33];
    __shared__ float ws[32][128];
    const int rowBase = blockIdx.x * 32;
    const int tid = threadIdx.x;
    const int ty = tid >> 5, tx = tid & 31;

    float acc[4][4];
#pragma unroll
    for (int i = 0; i < 4; ++i)
#pragma unroll
        for (int j = 0; j < 4; ++j) acc[i][j] = 0.f;

    for (int kb = 0; kb < 128; kb += 32) {
        __syncthreads();
        {
            const int row = tid >> 3;
            const int k4  = (tid & 7) * 4;
            const float4 v  = *reinterpret_cast<const float4*>(&g_y1[(rowBase + row) * 128 + kb + k4]);
            const float4 sc = *reinterpret_cast<const float4*>(&g_bns1[kb + k4]);
            const float4 sh = *reinterpret_cast<const float4*>(&g_bnh1[kb + k4]);
            xs[k4 + 0][row] = fmaf(v.x, sc.x, sh.x);
            xs[k4 + 1][row] = fmaf(v.y, sc.y, sh.y);
            xs[k4 + 2][row] = fmaf(v.z, sc.z, sh.z);
            xs[k4 + 3][row] = fmaf(v.w, sc.w, sh.w);
        }
        {
            const int col = tid >> 1;
            const int k0  = (tid & 1) * 16;
#pragma unroll
            for (int u = 0; u < 16; u += 4) {
                const float4 v = *reinterpret_cast<const float4*>(&W[col * 128 + kb + k0 + u]);
                ws[k0 + u + 0][col] = v.x; ws[k0 + u + 1][col] = v.y;
                ws[k0 + u + 2][col] = v.z; ws[k0 + u + 3][col] = v.w;
            }
        }
        __syncthreads();
#pragma unroll
        for (int kk = 0; kk < 32; ++kk) {
            float a[4], bb[4];
#pragma unroll
            for (int i = 0; i < 4; ++i) a[i] = xs[kk][ty * 4 + i];
#pragma unroll
            for (int j = 0; j < 4; ++j) bb[j] = ws[kk][tx + 32 * j];
#pragma unroll
            for (int i = 0; i < 4; ++i)
#pragma unroll
                for (int j = 0; j < 4; ++j) acc[i][j] = fmaf(a[i], bb[j], acc[i][j]);
        }
    }
#pragma unroll
    for (int j = 0; j < 4; ++j) {
        const int col = tx + 32 * j;
        const float bcol = bias[col];
#pragma unroll
        for (int i = 0; i < 4; ++i) {
            const int row = ty * 4 + i;
            g_y2[(rowBase + row) * 128 + col] = leaky(acc[i][j] + bcol);
        }
    }
}

// =====================================================================
// Layer 3: out = tanh( BN2(y2) @ pw3.T + pb3 )    K=128, N=64
// =====================================================================
__global__ void __launch_bounds__(256) gemm3_kernel(
    const float* __restrict__ W, const float* __restrict__ bias, float* __restrict__ out)
{
    __shared__ float xs[32][33];
    __shared__ float ws[32][64];
    const int rowBase = blockIdx.x * 32;
    const int tid = threadIdx.x;
    const int ty = tid >> 5, tx = tid & 31;

    float acc[4][2];
#pragma unroll
    for (int i = 0; i < 4; ++i) { acc[i][0] = 0.f; acc[i][1] = 0.f; }

    for (int kb = 0; kb < 128; kb += 32) {
        __syncthreads();
        {
            const int row = tid >> 3;
            const int k4  = (tid & 7) * 4;
            const float4 v  = *reinterpret_cast<const float4*>(&g_y2[(rowBase + row) * 128 + kb + k4]);
            const float4 sc = *reinterpret_cast<const float4*>(&g_bns2[kb + k4]);
            const float4 sh = *reinterpret_cast<const float4*>(&g_bnh2[kb + k4]);
            xs[k4 + 0][row] = fmaf(v.x, sc.x, sh.x);
            xs[k4 + 1][row] = fmaf(v.y, sc.y, sh.y);
            xs[k4 + 2][row] = fmaf(v.z, sc.z, sh.z);
            xs[k4 + 3][row] = fmaf(v.w, sc.w, sh.w);
        }
        {   // w tile: 64 cols x 32 k = 2048 elems, 8 per thread
            const int col = tid >> 2;          // 0..63
            const int k0  = (tid & 3) * 8;
#pragma unroll
            for (int u = 0; u < 8; u += 4) {
                const float4 v = *reinterpret_cast<const float4*>(&W[col * 128 + kb + k0 + u]);
                ws[k0 + u + 0][col] = v.x; ws[k0 + u + 1][col] = v.y;
                ws[k0 + u + 2][col] = v.z; ws[k0 + u + 3][col] = v.w;
            }
        }
        __syncthreads();
#pragma unroll
        for (int kk = 0; kk < 32; ++kk) {
            float a[4], bb[2];
#pragma unroll
            for (int i = 0; i < 4; ++i) a[i] = xs[kk][ty * 4 + i];
            bb[0] = ws[kk][tx]; bb[1] = ws[kk][tx + 32];
#pragma unroll
            for (int i = 0; i < 4; ++i) {
                acc[i][0] = fmaf(a[i], bb[0], acc[i][0]);
                acc[i][1] = fmaf(a[i], bb[1], acc[i][1]);
            }
        }
    }
#pragma unroll
    for (int j = 0; j < 2; ++j) {
        const int col = tx + 32 * j;
        const float bcol = bias[col];
#pragma unroll
        for (int i = 0; i < 4; ++i) {
            const int row = ty * 4 + i;
            out[(rowBase + row) * 64 + col] = tanhf(acc[i][j] + bcol);
        }
    }
}

// =====================================================================
extern "C" void kernel_launch(void* const* d_in, const int* in_sizes, int n_in,
                              void* d_out, int out_size)
{
    const float* noise  = (const float*)d_in[0];
    const float* labels = (const float*)d_in[1];
    const float* qparams= (const float*)d_in[2];
    const float* ew1 = (const float*)d_in[3];  const float* eb1 = (const float*)d_in[4];
    const float* ew2 = (const float*)d_in[5];  const float* eb2 = (const float*)d_in[6];
    const float* ew3 = (const float*)d_in[7];  const float* eb3 = (const float*)d_in[8];
    const float* pw1 = (const float*)d_in[9];  const float* pb1 = (const float*)d_in[10];
    const float* g1  = (const float*)d_in[11]; const float* be1 = (const float*)d_in[12];
    const float* pw2 = (const float*)d_in[13]; const float* pb2 = (const float*)d_in[14];
    const float* g2  = (const float*)d_in[15]; const float* be2 = (const float*)d_in[16];
    const float* pw3 = (const float*)d_in[17]; const float* pb3 = (const float*)d_in[18];
    float* out = (float*)d_out;

    embed_kernel<<<BATCH / 8, 256>>>(labels, ew1, eb1, ew2, eb2, ew3, eb3);
    qsim_kernel<<<BATCH * NGEN / 8, 256>>>(noise, qparams);
    gemm1_kernel<<<BATCH / 32, 256>>>(labels, pw1, pb1);
    bnstats1_kernel<<<128, 256>>>(g1, be1);
    gemm2_kernel<<<BATCH / 32, 256>>>(pw2, pb2);
    bnstats2_kernel<<<128, 256>>>(g2, be2);
    gemm3_kernel<<<BATCH / 32, 256>>>(pw3, pb3, out);
}

// round 3
// speedup vs baseline: 1.1475x; 1.1475x over previous
#include <cuda_runtime.h>
#include <math.h>

#define BATCH 2048
#define NQ    10
#define NGEN  4
#define DEPTH 6
#define PATCH 256
#define QOUT  1024
#define NCLS  10

typedef unsigned long long u64;

// ---------------- scratch (device globals; no allocation) ----------------
__device__ __align__(256) float g_angles[BATCH * 2 * NQ];   // (B,20)
__device__ __align__(256) float g_qf[BATCH * QOUT];         // (B,1024)
__device__ __align__(256) float g_y1[BATCH * 128];
__device__ __align__(256) float g_y2[BATCH * 128];
__device__ __align__(16)  float g_bns1[128], g_bnh1[128], g_bns2[128], g_bnh2[128];
__device__ __align__(16)  float g_wc[NGEN * DEPTH * NQ], g_ws[NGEN * DEPTH * NQ];
__device__ __align__(256) float g_ps[2][32][128];   // BN partial sums
__device__ __align__(256) float g_pq[2][32][128];   // BN partial sumsq

__device__ __forceinline__ float leaky(float x) { return x > 0.f ? x : 0.2f * x; }

// ---------------- packed f32x2 helpers (sm_100a) ----------------
__device__ __forceinline__ u64 pk2(float lo, float hi) {
    u64 r; asm("mov.b64 %0,{%1,%2};" : "=l"(r) : "f"(lo), "f"(hi)); return r;
}
__device__ __forceinline__ void upk2(float& lo, float& hi, u64 v) {
    asm("mov.b64 {%0,%1},%2;" : "=f"(lo), "=f"(hi) : "l"(v));
}
__device__ __forceinline__ u64 f2fma(u64 a, u64 b, u64 c) {
    u64 d; asm("fma.rn.f32x2 %0,%1,%2,%3;" : "=l"(d) : "l"(a), "l"(b), "l"(c)); return d;
}
__device__ __forceinline__ u64 f2mul(u64 a, u64 b) {
    u64 d; asm("mul.rn.f32x2 %0,%1,%2;" : "=l"(d) : "l"(a), "l"(b)); return d;
}

// =====================================================================
// Tiny kernel: precompute sincos of the 240 distinct variational angles.
// =====================================================================
__global__ void wtrig_kernel(const float* __restrict__ qp)
{
    const int i = threadIdx.x;
    if (i < NGEN * DEPTH * NQ) {
        float s, c; __sincosf(0.5f * qp[i], &s, &c);
        g_wc[i] = c; g_ws[i] = s;
    }
}

// =====================================================================
// Embedding MLP: labels(2048x10) -> 32 -> 64 -> 20 angles (tanh * pi)
// =====================================================================
__global__ void __launch_bounds__(256) embed_kernel(
    const float* __restrict__ lab,
    const float* __restrict__ ew1, const float* __restrict__ eb1,
    const float* __restrict__ ew2, const float* __restrict__ eb2,
    const float* __restrict__ ew3, const float* __restrict__ eb3)
{
    const int wip  = threadIdx.x >> 5;
    const int row  = blockIdx.x * 8 + wip;
    const unsigned lane = threadIdx.x & 31u;
    __shared__ float h1s[8][32];
    __shared__ float h2s[8][64];

    float lv[NCLS];
    const float* L = lab + row * NCLS;
#pragma unroll
    for (int c = 0; c < NCLS; ++c) lv[c] = L[c];

    {
        float a = eb1[lane];
#pragma unroll
        for (int c = 0; c < NCLS; ++c) a = fmaf(lv[c], ew1[lane * NCLS + c], a);
        h1s[wip][lane] = leaky(a);
    }
    __syncwarp();
#pragma unroll
    for (int j = 0; j < 2; ++j) {
        const int o = lane + 32 * j;
        float a = eb2[o];
#pragma unroll
        for (int i = 0; i < 32; ++i) a = fmaf(h1s[wip][i], ew2[o * 32 + i], a);
        h2s[wip][o] = leaky(a);
    }
    __syncwarp();
    if (lane < 2 * NQ) {
        float a = eb3[lane];
#pragma unroll
        for (int i = 0; i < 64; ++i) a = fmaf(h2s[wip][i], ew3[lane * 64 + i], a);
        g_angles[row * 2 * NQ + lane] = tanhf(a) * 3.14159265358979323846f;
    }
}

// =====================================================================
// Quantum circuit simulator: one warp per (batch, generator).
// State: 1024 complex amps packed as f32x2 (lo=re, hi=im).
// flat index i = r*32 + lane; qubit q <-> bit 9-q.
// =====================================================================

// real-state RY (prologue; state known real)
template <int B>
__device__ __forceinline__ void ry_r(float (&re)[32], float c, float s, unsigned lane)
{
    if (B >= 5) {
        const int m = 1 << (B - 5);
#pragma unroll
        for (int r = 0; r < 32; ++r) {
            if (!(r & m)) {
                const float a0 = re[r], a1 = re[r | m];
                re[r]     = fmaf(-s, a1, c * a0);
                re[r | m] = fmaf( s, a0, c * a1);
            }
        }
    } else {
        const unsigned mk = 1u << B;
        const float t = (lane & mk) ? s : -s;
#pragma unroll
        for (int r = 0; r < 32; ++r) {
            const float p = __shfl_xor_sync(0xffffffffu, re[r], mk);
            re[r] = fmaf(t, p, c * re[r]);
        }
    }
}

// packed complex RY
template <int B>
__device__ __forceinline__ void ry_p(u64 (&v)[32], u64 c2, u64 s2, u64 ns2, unsigned lane)
{
    if (B >= 5) {
        const int m = 1 << (B - 5);
#pragma unroll
        for (int r = 0; r < 32; ++r) {
            if (!(r & m)) {
                const u64 a0 = v[r], a1 = v[r | m];
                v[r]     = f2fma(ns2, a1, f2mul(c2, a0));
                v[r | m] = f2fma(s2,  a0, f2mul(c2, a1));
            }
        }
    } else {
        const unsigned mk = 1u << B;
        const u64 t2 = (lane & mk) ? s2 : ns2;
#pragma unroll
        for (int r = 0; r < 32; ++r) {
            const u64 p = __shfl_xor_sync(0xffffffffu, v[r], mk);
            v[r] = f2fma(t2, p, f2mul(c2, v[r]));
        }
    }
}

__global__ void __launch_bounds__(256, 2) qsim_kernel(const float* __restrict__ noise)
{
    const int w = (blockIdx.x * 256 + threadIdx.x) >> 5;   // 0..8191
    const unsigned lane = threadIdx.x & 31u;
    const int b = w >> 2, g = w & 3;
    const float* nz = noise + b * NQ;
    const float* an = g_angles + b * 2 * NQ;

    float re[32];
#pragma unroll
    for (int r = 0; r < 32; ++r) re[r] = 0.f;
    if (lane == 0) re[0] = 1.f;

    float c, s;
    // --- 10 noise RYs + 10 angle RYs on real state (RZs commuted after) ---
#define RYN(q) { __sincosf(0.5f * nz[q], &s, &c); ry_r<9 - (q)>(re, c, s, lane); }
    RYN(0) RYN(1) RYN(2) RYN(3) RYN(4) RYN(5) RYN(6) RYN(7) RYN(8) RYN(9)
#undef RYN
#define RYA(q) { __sincosf(0.5f * an[q], &s, &c); ry_r<9 - (q)>(re, c, s, lane); }
    RYA(0) RYA(1) RYA(2) RYA(3) RYA(4) RYA(5) RYA(6) RYA(7) RYA(8) RYA(9)
#undef RYA

    // --- fused RZ: total phase phi(i) = sum_q sign_q(i) * theta_q/2 ---
    // sign_q = +1 if bit(9-q) of flat index set. Amp (real) -> re*(cos, sin).
    const float* az = an + NQ;
    float phl = 0.f;
#pragma unroll
    for (int j = 0; j < 5; ++j) {          // lane bit j <-> qubit 9-j
        const float t = 0.5f * az[9 - j];
        phl += ((lane >> j) & 1u) ? t : -t;
    }
    float a0 = 0.5f * az[4], a1 = 0.5f * az[3], a2 = 0.5f * az[2],
          a3 = 0.5f * az[1], a4 = 0.5f * az[0];   // reg bit j <-> qubit 4-j
    const float base = phl - (a0 + a1 + a2 + a3 + a4);

    u64 v[32];
#pragma unroll
    for (int r = 0; r < 32; ++r) {
        float S = 0.f;
        if (r & 1)  S += a0;
        if (r & 2)  S += a1;
        if (r & 4)  S += a2;
        if (r & 8)  S += a3;
        if (r & 16) S += a4;
        const float ph = fmaf(2.f, S, base);
        float sn, cs; __sincosf(ph, &sn, &cs);
        v[r] = f2mul(pk2(re[r], re[r]), pk2(cs, sn));
    }

    // CZ chain sign: flip iff popc(i & (i>>1)) odd. Decompose into per-lane
    // factors fA (even r) / fB (odd r) times compile-time reg parity.
    const bool pA = (__popc(lane & (lane >> 1)) & 1) != 0;
    const bool pB = pA ^ (((lane >> 4) & 1u) != 0);
    const float fA = pA ? -1.f : 1.f, fB = pB ? -1.f : 1.f;
    const u64 uA  = pk2(fA, fA),  uB  = pk2(fB, fB);
    const u64 uAn = pk2(-fA, -fA), uBn = pk2(-fB, -fB);

    const float* wc = g_wc + g * DEPTH * NQ;
    const float* wsn = g_ws + g * DEPTH * NQ;

    // --- 6 variational layers (packed) ---
#pragma unroll 1
    for (int l = 0; l < DEPTH; ++l) {
        const float* lc = wc + l * NQ;
        const float* ls = wsn + l * NQ;
#define RYW(q) { const float cc = lc[q], ss = ls[q]; \
                 ry_p<9 - (q)>(v, pk2(cc, cc), pk2(ss, ss), pk2(-ss, -ss), lane); }
        RYW(0) RYW(1) RYW(2) RYW(3) RYW(4) RYW(5) RYW(6) RYW(7) RYW(8) RYW(9)
#undef RYW
#pragma unroll
        for (int r = 0; r < 32; ++r) {
            const bool srg = ((__popc(r & (r >> 1)) & 1) != 0);
            const u64 f = (r & 1) ? (srg ? uBn : uB) : (srg ? uAn : uA);
            v[r] = f2mul(v[r], f);
        }
    }

    // --- output: probs of first 256 amps (regs 0..7), normalized by max ---
    float p[8];
    float mx = 0.f;
#pragma unroll
    for (int r = 0; r < 8; ++r) {
        const u64 sq = f2mul(v[r], v[r]);
        float x, y; upk2(x, y, sq);
        p[r] = x + y;
        mx = fmaxf(mx, p[r]);
    }
#pragma unroll
    for (int o = 16; o; o >>= 1) mx = fmaxf(mx, __shfl_xor_sync(0xffffffffu, mx, o));
    const float inv = 1.0f / mx;
    float* dst = g_qf + b * QOUT + g * PATCH;
#pragma unroll
    for (int r = 0; r < 8; ++r) dst[r * 32 + lane] = p[r] * inv;
}

// =====================================================================
// Layer 1: y1 = leaky([qf | labels] @ pw1.T + pb1)   K=1034
// 16 rows x 128 cols per block -> 128 blocks (full chip wave).
// =====================================================================
__global__ void __launch_bounds__(256) gemm1_kernel(
    const float* __restrict__ lab, const float* __restrict__ W, const float* __restrict__ bias)
{
    __shared__ float xs[32][17];
    __shared__ float ws[32][128];
    __shared__ float labs[16][NCLS];
    const int rowBase = blockIdx.x * 16;
    const int tid = threadIdx.x;
    const int ty = tid >> 5, tx = tid & 31;

    float acc[2][4];
#pragma unroll
    for (int i = 0; i < 2; ++i)
#pragma unroll
        for (int j = 0; j < 4; ++j) acc[i][j] = 0.f;

    for (int t = tid; t < 16 * NCLS; t += 256)
        labs[t / NCLS][t % NCLS] = lab[(rowBase + t / NCLS) * NCLS + t % NCLS];

    for (int kb = 0; kb < QOUT; kb += 32) {
        __syncthreads();
        if (tid < 128) {   // x tile: 16 rows x 32 k
            const int row = tid >> 3;
            const int k4  = (tid & 7) * 4;
            const float4 vv = *reinterpret_cast<const float4*>(&g_qf[(rowBase + row) * QOUT + kb + k4]);
            xs[k4 + 0][row] = vv.x; xs[k4 + 1][row] = vv.y;
            xs[k4 + 2][row] = vv.z; xs[k4 + 3][row] = vv.w;
        }
        {   // w tile: 128 cols x 32 k (row length 1034 -> 8B alignment)
            const int col = tid >> 1;
            const int k0  = (tid & 1) * 16;
#pragma unroll
            for (int u = 0; u < 16; u += 2) {
                const float2 vv = *reinterpret_cast<const float2*>(&W[col * 1034 + kb + k0 + u]);
                ws[k0 + u + 0][col] = vv.x;
                ws[k0 + u + 1][col] = vv.y;
            }
        }
        __syncthreads();
#pragma unroll
        for (int kk = 0; kk < 32; ++kk) {
            const float x0 = xs[kk][ty * 2 + 0];
            const float x1 = xs[kk][ty * 2 + 1];
            float bb[4];
#pragma unroll
            for (int j = 0; j < 4; ++j) bb[j] = ws[kk][tx + 32 * j];
#pragma unroll
            for (int j = 0; j < 4; ++j) {
                acc[0][j] = fmaf(x0, bb[j], acc[0][j]);
                acc[1][j] = fmaf(x1, bb[j], acc[1][j]);
            }
        }
    }

#pragma unroll
    for (int j = 0; j < 4; ++j) {
        const int col = tx + 32 * j;
        float wt[NCLS];
#pragma unroll
        for (int cI = 0; cI < NCLS; ++cI) wt[cI] = W[col * 1034 + QOUT + cI];
        const float bcol = bias[col];
#pragma unroll
        for (int i = 0; i < 2; ++i) {
            const int row = ty * 2 + i;
            float vv = acc[i][j] + bcol;
#pragma unroll
            for (int cI = 0; cI < NCLS; ++cI) vv = fmaf(labs[row][cI], wt[cI], vv);
            g_y1[(rowBase + row) * 128 + col] = leaky(vv);
        }
    }
}

// =====================================================================
// BatchNorm stats, two-stage coalesced:
// stage 1: 32 blocks, each block reduces 64 rows -> per-col partials
// stage 2: 1 block finalizes scale/shift
// =====================================================================
__global__ void __launch_bounds__(256) bnpart_kernel(int which)
{
    const float* src = which ? g_y2 : g_y1;
    const int tid = threadIdx.x;
    const int c = tid & 127, rh = tid >> 7;
    float s1 = 0.f, s2 = 0.f;
    const int rEnd = blockIdx.x * 64 + 64;
    for (int r = blockIdx.x * 64 + rh; r < rEnd; r += 2) {
        const float vv = src[r * 128 + c];
        s1 += vv; s2 = fmaf(vv, vv, s2);
    }
    __shared__ float sh[2][2][128];
    sh[rh][0][c] = s1; sh[rh][1][c] = s2;
    __syncthreads();
    if (tid < 128) {
        g_ps[which][blockIdx.x][tid] = sh[0][0][tid] + sh[1][0][tid];
        g_pq[which][blockIdx.x][tid] = sh[0][1][tid] + sh[1][1][tid];
    }
}

__global__ void __launch_bounds__(128) bnfin_kernel(
    int which, const float* __restrict__ gamma, const float* __restrict__ beta)
{
    const int c = threadIdx.x;
    float s1 = 0.f, s2 = 0.f;
#pragma unroll
    for (int b = 0; b < 32; ++b) { s1 += g_ps[which][b][c]; s2 += g_pq[which][b][c]; }
    const float mu   = s1 * (1.f / BATCH);
    const float var  = s2 * (1.f / BATCH) - mu * mu;
    const float rstd = rsqrtf(var + 1e-5f);
    const float sc   = gamma[c] * rstd;
    if (which) { g_bns2[c] = sc; g_bnh2[c] = beta[c] - mu * sc; }
    else       { g_bns1[c] = sc; g_bnh1[c] = beta[c] - mu * sc; }
}

// =====================================================================
// Layer 2: y2 = leaky( BN1(y1) @ pw2.T + pb2 )    K=128
// =====================================================================
__global__ void __launch_bounds__(256) gemm2_kernel(
    const float* __restrict__ W, const float* __restrict__ bias)
{
    __shared__ float xs[32][33];
    __shared__ float ws[32][128];
    const int rowBase = blockIdx.x * 32;
    const int tid = threadIdx.x;
    const int ty = tid >> 5, tx = tid & 31;

    float acc[4][4];
#pragma unroll
    for (int i = 0; i < 4; ++i)
#pragma unroll
        for (int j = 0; j < 4; ++j) acc[i][j] = 0.f;

    for (int kb = 0; kb < 128; kb += 32) {
        __syncthreads();
        {
            const int row = tid >> 3;
            const int k4  = (tid & 7) * 4;
            const float4 vv = *reinterpret_cast<const float4*>(&g_y1[(rowBase + row) * 128 + kb + k4]);
            const float4 sc = *reinterpret_cast<const float4*>(&g_bns1[kb + k4]);
            const float4 sh = *reinterpret_cast<const float4*>(&g_bnh1[kb + k4]);
            xs[k4 + 0][row] = fmaf(vv.x, sc.x, sh.x);
            xs[k4 + 1][row] = fmaf(vv.y, sc.y, sh.y);
            xs[k4 + 2][row] = fmaf(vv.z, sc.z, sh.z);
            xs[k4 + 3][row] = fmaf(vv.w, sc.w, sh.w);
        }
        {
            const int col = tid >> 1;
            const int k0  = (tid & 1) * 16;
#pragma unroll
            for (int u = 0; u < 16; u += 4) {
                const float4 vv = *reinterpret_cast<const float4*>(&W[col * 128 + kb + k0 + u]);
                ws[k0 + u + 0][col] = vv.x; ws[k0 + u + 1][col] = vv.y;
                ws[k0 + u + 2][col] = vv.z; ws[k0 + u + 3][col] = vv.w;
            }
        }
        __syncthreads();
#pragma unroll
        for (int kk = 0; kk < 32; ++kk) {
            float a[4], bb[4];
#pragma unroll
            for (int i = 0; i < 4; ++i) a[i] = xs[kk][ty * 4 + i];
#pragma unroll
            for (int j = 0; j < 4; ++j) bb[j] = ws[kk][tx + 32 * j];
#pragma unroll
            for (int i = 0; i < 4; ++i)
#pragma unroll
                for (int j = 0; j < 4; ++j) acc[i][j] = fmaf(a[i], bb[j], acc[i][j]);
        }
    }
#pragma unroll
    for (int j = 0; j < 4; ++j) {
        const int col = tx + 32 * j;
        const float bcol = bias[col];
#pragma unroll
        for (int i = 0; i < 4; ++i) {
            const int row = ty * 4 + i;
            g_y2[(rowBase + row) * 128 + col] = leaky(acc[i][j] + bcol);
        }
    }
}

// =====================================================================
// Layer 3: out = tanh( BN2(y2) @ pw3.T + pb3 )    K=128, N=64
// =====================================================================
__global__ void __launch_bounds__(256) gemm3_kernel(
    const float* __restrict__ W, const float* __restrict__ bias, float* __restrict__ out)
{
    __shared__ float xs[32][33];
    __shared__ float ws[32][64];
    const int rowBase = blockIdx.x * 32;
    const int tid = threadIdx.x;
    const int ty = tid >> 5, tx = tid & 31;

    float acc[4][2];
#pragma unroll
    for (int i = 0; i < 4; ++i) { acc[i][0] = 0.f; acc[i][1] = 0.f; }

    for (int kb = 0; kb < 128; kb += 32) {
        __syncthreads();
        {
            const int row = tid >> 3;
            const int k4  = (tid & 7) * 4;
            const float4 vv = *reinterpret_cast<const float4*>(&g_y2[(rowBase + row) * 128 + kb + k4]);
            const float4 sc = *reinterpret_cast<const float4*>(&g_bns2[kb + k4]);
            const float4 sh = *reinterpret_cast<const float4*>(&g_bnh2[kb + k4]);
            xs[k4 + 0][row] = fmaf(vv.x, sc.x, sh.x);
            xs[k4 + 1][row] = fmaf(vv.y, sc.y, sh.y);
            xs[k4 + 2][row] = fmaf(vv.z, sc.z, sh.z);
            xs[k4 + 3][row] = fmaf(vv.w, sc.w, sh.w);
        }
        {
            const int col = tid >> 2;
            const int k0  = (tid & 3) * 8;
#pragma unroll
            for (int u = 0; u < 8; u += 4) {
                const float4 vv = *reinterpret_cast<const float4*>(&W[col * 128 + kb + k0 + u]);
                ws[k0 + u + 0][col] = vv.x; ws[k0 + u + 1][col] = vv.y;
                ws[k0 + u + 2][col] = vv.z; ws[k0 + u + 3][col] = vv.w;
            }
        }
        __syncthreads();
#pragma unroll
        for (int kk = 0; kk < 32; ++kk) {
            float a[4], bb[2];
#pragma unroll
            for (int i = 0; i < 4; ++i) a[i] = xs[kk][ty * 4 + i];
            bb[0] = ws[kk][tx]; bb[1] = ws[kk][tx + 32];
#pragma unroll
            for (int i = 0; i < 4; ++i) {
                acc[i][0] = fmaf(a[i], bb[0], acc[i][0]);
                acc[i][1] = fmaf(a[i], bb[1], acc[i][1]);
            }
        }
    }
#pragma unroll
    for (int j = 0; j < 2; ++j) {
        const int col = tx + 32 * j;
        const float bcol = bias[col];
#pragma unroll
        for (int i = 0; i < 4; ++i) {
            const int row = ty * 4 + i;
            out[(rowBase + row) * 64 + col] = tanhf(acc[i][j] + bcol);
        }
    }
}

// =====================================================================
extern "C" void kernel_launch(void* const* d_in, const int* in_sizes, int n_in,
                              void* d_out, int out_size)
{
    const float* noise  = (const float*)d_in[0];
    const float* labels = (const float*)d_in[1];
    const float* qparams= (const float*)d_in[2];
    const float* ew1 = (const float*)d_in[3];  const float* eb1 = (const float*)d_in[4];
    const float* ew2 = (const float*)d_in[5];  const float* eb2 = (const float*)d_in[6];
    const float* ew3 = (const float*)d_in[7];  const float* eb3 = (const float*)d_in[8];
    const float* pw1 = (const float*)d_in[9];  const float* pb1 = (const float*)d_in[10];
    const float* g1  = (const float*)d_in[11]; const float* be1 = (const float*)d_in[12];
    const float* pw2 = (const float*)d_in[13]; const float* pb2 = (const float*)d_in[14];
    const float* g2  = (const float*)d_in[15]; const float* be2 = (const float*)d_in[16];
    const float* pw3 = (const float*)d_in[17]; const float* pb3 = (const float*)d_in[18];
    float* out = (float*)d_out;

    wtrig_kernel<<<1, 256>>>(qparams);
    embed_kernel<<<BATCH / 8, 256>>>(labels, ew1, eb1, ew2, eb2, ew3, eb3);
    qsim_kernel<<<BATCH * NGEN / 8, 256>>>(noise);
    gemm1_kernel<<<BATCH / 16, 256>>>(labels, pw1, pb1);
    bnpart_kernel<<<32, 256>>>(0);
    bnfin_kernel<<<1, 128>>>(0, g1, be1);
    gemm2_kernel<<<BATCH / 32, 256>>>(pw2, pb2);
    bnpart_kernel<<<32, 256>>>(1);
    bnfin_kernel<<<1, 128>>>(1, g2, be2);
    gemm3_kernel<<<BATCH / 32, 256>>>(pw3, pb3, out);
}

// round 4
// speedup vs baseline: 1.3274x; 1.1567x over previous
#include <cuda_runtime.h>
#include <math.h>

#define BATCH 2048
#define NQ    10
#define NGEN  4
#define DEPTH 6
#define PATCH 256
#define QOUT  1024
#define NCLS  10

typedef unsigned long long u64;

// ---------------- scratch (device globals; no allocation) ----------------
__device__ __align__(256) float g_angles[BATCH * 2 * NQ];   // (B,20)
__device__ __align__(256) float g_qf[BATCH * QOUT];         // (B,1024)
__device__ __align__(256) float g_y1[BATCH * 128];
__device__ __align__(256) float g_y2[BATCH * 128];
__device__ __align__(16)  float g_bns1[128], g_bnh1[128], g_bns2[128], g_bnh2[128];
__device__ __align__(16)  float g_wc[NGEN * DEPTH * NQ], g_ws[NGEN * DEPTH * NQ];
__device__ __align__(256) float g_ps[2][32][128];   // BN partial sums
__device__ __align__(256) float g_pq[2][32][128];   // BN partial sumsq
__device__ __align__(256) float g_p1[4][BATCH * 128];  // gemm1 split-K partials

__device__ __forceinline__ float leaky(float x) { return x > 0.f ? x : 0.2f * x; }

// ---------------- packed f32x2 helpers ----------------
__device__ __forceinline__ u64 pk2(float lo, float hi) {
    u64 r; asm("mov.b64 %0,{%1,%2};" : "=l"(r) : "f"(lo), "f"(hi)); return r;
}
__device__ __forceinline__ void upk2(float& lo, float& hi, u64 v) {
    asm("mov.b64 {%0,%1},%2;" : "=f"(lo), "=f"(hi) : "l"(v));
}
__device__ __forceinline__ u64 f2fma(u64 a, u64 b, u64 c) {
    u64 d; asm("fma.rn.f32x2 %0,%1,%2,%3;" : "=l"(d) : "l"(a), "l"(b), "l"(c)); return d;
}
__device__ __forceinline__ u64 f2mul(u64 a, u64 b) {
    u64 d; asm("mul.rn.f32x2 %0,%1,%2;" : "=l"(d) : "l"(a), "l"(b)); return d;
}

// =====================================================================
// Embedding MLP (blocks 0..255) + wtrig (block 256).
// =====================================================================
__global__ void __launch_bounds__(256) embed_kernel(
    const float* __restrict__ lab, const float* __restrict__ qp,
    const float* __restrict__ ew1, const float* __restrict__ eb1,
    const float* __restrict__ ew2, const float* __restrict__ eb2,
    const float* __restrict__ ew3, const float* __restrict__ eb3)
{
    if (blockIdx.x == 256) {               // precompute 240 variational sincos
        const int i = threadIdx.x;
        if (i < NGEN * DEPTH * NQ) {
            float s, c; __sincosf(0.5f * qp[i], &s, &c);
            g_wc[i] = c; g_ws[i] = s;
        }
        return;
    }
    const int wip  = threadIdx.x >> 5;
    const int row  = blockIdx.x * 8 + wip;
    const unsigned lane = threadIdx.x & 31u;
    __shared__ float h1s[8][32];
    __shared__ float h2s[8][64];

    float lv[NCLS];
    const float* L = lab + row * NCLS;
#pragma unroll
    for (int c = 0; c < NCLS; ++c) lv[c] = L[c];

    {
        float a = eb1[lane];
#pragma unroll
        for (int c = 0; c < NCLS; ++c) a = fmaf(lv[c], ew1[lane * NCLS + c], a);
        h1s[wip][lane] = leaky(a);
    }
    __syncwarp();
#pragma unroll
    for (int j = 0; j < 2; ++j) {
        const int o = lane + 32 * j;
        float a = eb2[o];
#pragma unroll
        for (int i = 0; i < 32; ++i) a = fmaf(h1s[wip][i], ew2[o * 32 + i], a);
        h2s[wip][o] = leaky(a);
    }
    __syncwarp();
    if (lane < 2 * NQ) {
        float a = eb3[lane];
#pragma unroll
        for (int i = 0; i < 64; ++i) a = fmaf(h2s[wip][i], ew3[lane * 64 + i], a);
        g_angles[row * 2 * NQ + lane] = tanhf(a) * 3.14159265358979323846f;
    }
}

// =====================================================================
// Quantum circuit simulator (unchanged from R3; profiled next round).
// =====================================================================
template <int B>
__device__ __forceinline__ void ry_r(float (&re)[32], float c, float s, unsigned lane)
{
    if (B >= 5) {
        const int m = 1 << (B - 5);
#pragma unroll
        for (int r = 0; r < 32; ++r) {
            if (!(r & m)) {
                const float a0 = re[r], a1 = re[r | m];
                re[r]     = fmaf(-s, a1, c * a0);
                re[r | m] = fmaf( s, a0, c * a1);
            }
        }
    } else {
        const unsigned mk = 1u << B;
        const float t = (lane & mk) ? s : -s;
#pragma unroll
        for (int r = 0; r < 32; ++r) {
            const float p = __shfl_xor_sync(0xffffffffu, re[r], mk);
            re[r] = fmaf(t, p, c * re[r]);
        }
    }
}

template <int B>
__device__ __forceinline__ void ry_p(u64 (&v)[32], u64 c2, u64 s2, u64 ns2, unsigned lane)
{
    if (B >= 5) {
        const int m = 1 << (B - 5);
#pragma unroll
        for (int r = 0; r < 32; ++r) {
            if (!(r & m)) {
                const u64 a0 = v[r], a1 = v[r | m];
                v[r]     = f2fma(ns2, a1, f2mul(c2, a0));
                v[r | m] = f2fma(s2,  a0, f2mul(c2, a1));
            }
        }
    } else {
        const unsigned mk = 1u << B;
        const u64 t2 = (lane & mk) ? s2 : ns2;
#pragma unroll
        for (int r = 0; r < 32; ++r) {
            const u64 p = __shfl_xor_sync(0xffffffffu, v[r], mk);
            v[r] = f2fma(t2, p, f2mul(c2, v[r]));
        }
    }
}

__global__ void __launch_bounds__(256, 2) qsim_kernel(const float* __restrict__ noise)
{
    const int w = (blockIdx.x * 256 + threadIdx.x) >> 5;
    const unsigned lane = threadIdx.x & 31u;
    const int b = w >> 2, g = w & 3;
    const float* nz = noise + b * NQ;
    const float* an = g_angles + b * 2 * NQ;

    float re[32];
#pragma unroll
    for (int r = 0; r < 32; ++r) re[r] = 0.f;
    if (lane == 0) re[0] = 1.f;

    float c, s;
#define RYN(q) { __sincosf(0.5f * nz[q], &s, &c); ry_r<9 - (q)>(re, c, s, lane); }
    RYN(0) RYN(1) RYN(2) RYN(3) RYN(4) RYN(5) RYN(6) RYN(7) RYN(8) RYN(9)
#undef RYN
#define RYA(q) { __sincosf(0.5f * an[q], &s, &c); ry_r<9 - (q)>(re, c, s, lane); }
    RYA(0) RYA(1) RYA(2) RYA(3) RYA(4) RYA(5) RYA(6) RYA(7) RYA(8) RYA(9)
#undef RYA

    const float* az = an + NQ;
    float phl = 0.f;
#pragma unroll
    for (int j = 0; j < 5; ++j) {
        const float t = 0.5f * az[9 - j];
        phl += ((lane >> j) & 1u) ? t : -t;
    }
    float a0 = 0.5f * az[4], a1 = 0.5f * az[3], a2 = 0.5f * az[2],
          a3 = 0.5f * az[1], a4 = 0.5f * az[0];
    const float base = phl - (a0 + a1 + a2 + a3 + a4);

    u64 v[32];
#pragma unroll
    for (int r = 0; r < 32; ++r) {
        float S = 0.f;
        if (r & 1)  S += a0;
        if (r & 2)  S += a1;
        if (r & 4)  S += a2;
        if (r & 8)  S += a3;
        if (r & 16) S += a4;
        const float ph = fmaf(2.f, S, base);
        float sn, cs; __sincosf(ph, &sn, &cs);
        v[r] = f2mul(pk2(re[r], re[r]), pk2(cs, sn));
    }

    const bool pA = (__popc(lane & (lane >> 1)) & 1) != 0;
    const bool pB = pA ^ (((lane >> 4) & 1u) != 0);
    const float fA = pA ? -1.f : 1.f, fB = pB ? -1.f : 1.f;
    const u64 uA  = pk2(fA, fA),   uB  = pk2(fB, fB);
    const u64 uAn = pk2(-fA, -fA), uBn = pk2(-fB, -fB);

    const float* wc  = g_wc + g * DEPTH * NQ;
    const float* wsn = g_ws + g * DEPTH * NQ;

#pragma unroll 1
    for (int l = 0; l < DEPTH; ++l) {
        const float* lc = wc + l * NQ;
        const float* ls = wsn + l * NQ;
#define RYW(q) { const float cc = lc[q], ss = ls[q]; \
                 ry_p<9 - (q)>(v, pk2(cc, cc), pk2(ss, ss), pk2(-ss, -ss), lane); }
        RYW(0) RYW(1) RYW(2) RYW(3) RYW(4) RYW(5) RYW(6) RYW(7) RYW(8) RYW(9)
#undef RYW
#pragma unroll
        for (int r = 0; r < 32; ++r) {
            const bool srg = ((__popc(r & (r >> 1)) & 1) != 0);
            const u64 f = (r & 1) ? (srg ? uBn : uB) : (srg ? uAn : uA);
            v[r] = f2mul(v[r], f);
        }
    }

    float p[8];
    float mx = 0.f;
#pragma unroll
    for (int r = 0; r < 8; ++r) {
        const u64 sq = f2mul(v[r], v[r]);
        float x, y; upk2(x, y, sq);
        p[r] = x + y;
        mx = fmaxf(mx, p[r]);
    }
#pragma unroll
    for (int o = 16; o; o >>= 1) mx = fmaxf(mx, __shfl_xor_sync(0xffffffffu, mx, o));
    const float inv = 1.0f / mx;
    float* dst = g_qf + b * QOUT + g * PATCH;
#pragma unroll
    for (int r = 0; r < 8; ++r) dst[r * 32 + lane] = p[r] * inv;
}

// =====================================================================
// gemm1 split-K partial: 128 blocks = 32 row-tiles x 4 k-chunks.
// Tile: 64 rows x 128 cols x 256 k.  Microtile 8x4, vector LDS.
// =====================================================================
__global__ void __launch_bounds__(256) gemm1p_kernel(const float* __restrict__ W)
{
    __shared__ float xs[32][64];    // [k][row]
    __shared__ float ws[32][128];   // [k][col]
    const int rowBase = (blockIdx.x >> 2) * 64;
    const int kc      = (blockIdx.x & 3) * 256;
    const int tid = threadIdx.x;
    const int ty = tid >> 5, tx = tid & 31;   // ty: 8 row-groups, tx: col/4

    float acc[8][4];
#pragma unroll
    for (int i = 0; i < 8; ++i)
#pragma unroll
        for (int j = 0; j < 4; ++j) acc[i][j] = 0.f;

    for (int kb = 0; kb < 256; kb += 32) {
        __syncthreads();
        // x tile: 64 rows x 32 k (2 float4 per thread)
#pragma unroll
        for (int t = 0; t < 2; ++t) {
            const int idx = tid + t * 256;        // 0..511
            const int row = idx & 63;
            const int k4  = (idx >> 6) * 4;
            const float4 vv = *reinterpret_cast<const float4*>(
                &g_qf[(rowBase + row) * QOUT + kc + kb + k4]);
            xs[k4 + 0][row] = vv.x; xs[k4 + 1][row] = vv.y;
            xs[k4 + 2][row] = vv.z; xs[k4 + 3][row] = vv.w;
        }
        // w tile: 128 cols x 32 k (float2, rows are 8B aligned)
        {
            const int col = tid >> 1;
            const int k0  = (tid & 1) * 16;
#pragma unroll
            for (int u = 0; u < 16; u += 2) {
                const float2 vv = *reinterpret_cast<const float2*>(
                    &W[col * 1034 + kc + kb + k0 + u]);
                ws[k0 + u + 0][col] = vv.x;
                ws[k0 + u + 1][col] = vv.y;
            }
        }
        __syncthreads();
#pragma unroll
        for (int kk = 0; kk < 32; ++kk) {
            const float4 A0 = *reinterpret_cast<const float4*>(&xs[kk][ty * 8]);
            const float4 A1 = *reinterpret_cast<const float4*>(&xs[kk][ty * 8 + 4]);
            const float4 B  = *reinterpret_cast<const float4*>(&ws[kk][tx * 4]);
            const float a[8] = {A0.x, A0.y, A0.z, A0.w, A1.x, A1.y, A1.z, A1.w};
            const float bb[4] = {B.x, B.y, B.z, B.w};
#pragma unroll
            for (int i = 0; i < 8; ++i)
#pragma unroll
                for (int j = 0; j < 4; ++j) acc[i][j] = fmaf(a[i], bb[j], acc[i][j]);
        }
    }

    float* dst = g_p1[blockIdx.x & 3];
#pragma unroll
    for (int i = 0; i < 8; ++i) {
        const int row = rowBase + ty * 8 + i;
        float4 vv = make_float4(acc[i][0], acc[i][1], acc[i][2], acc[i][3]);
        *reinterpret_cast<float4*>(&dst[row * 128 + tx * 4]) = vv;
    }
}

// reduce partials + bias + label tail + leaky -> y1
__global__ void __launch_bounds__(256) reduce1_kernel(
    const float* __restrict__ lab, const float* __restrict__ W, const float* __restrict__ bias)
{
    const int t = blockIdx.x * 256 + threadIdx.x;   // 0..65535
    const int row = t >> 5;
    const int cg  = (t & 31) * 4;
    float4 s = *reinterpret_cast<const float4*>(&g_p1[0][row * 128 + cg]);
    const float4 s1 = *reinterpret_cast<const float4*>(&g_p1[1][row * 128 + cg]);
    const float4 s2 = *reinterpret_cast<const float4*>(&g_p1[2][row * 128 + cg]);
    const float4 s3 = *reinterpret_cast<const float4*>(&g_p1[3][row * 128 + cg]);
    s.x += s1.x + s2.x + s3.x;  s.y += s1.y + s2.y + s3.y;
    s.z += s1.z + s2.z + s3.z;  s.w += s1.w + s2.w + s3.w;
    const float4 bv = *reinterpret_cast<const float4*>(&bias[cg]);
    s.x += bv.x; s.y += bv.y; s.z += bv.z; s.w += bv.w;
    float lv[NCLS];
#pragma unroll
    for (int c = 0; c < NCLS; ++c) lv[c] = lab[row * NCLS + c];
#pragma unroll
    for (int c = 0; c < NCLS; ++c) {
        s.x = fmaf(lv[c], W[(cg + 0) * 1034 + QOUT + c], s.x);
        s.y = fmaf(lv[c], W[(cg + 1) * 1034 + QOUT + c], s.y);
        s.z = fmaf(lv[c], W[(cg + 2) * 1034 + QOUT + c], s.z);
        s.w = fmaf(lv[c], W[(cg + 3) * 1034 + QOUT + c], s.w);
    }
    s.x = leaky(s.x); s.y = leaky(s.y); s.z = leaky(s.z); s.w = leaky(s.w);
    *reinterpret_cast<float4*>(&g_y1[row * 128 + cg]) = s;
}

// =====================================================================
// BN stats (two-stage, coalesced)
// =====================================================================
__global__ void __launch_bounds__(256) bnpart_kernel(int which)
{
    const float* src = which ? g_y2 : g_y1;
    const int tid = threadIdx.x;
    const int c = tid & 127, rh = tid >> 7;
    float s1 = 0.f, s2 = 0.f;
    const int rEnd = blockIdx.x * 64 + 64;
    for (int r = blockIdx.x * 64 + rh; r < rEnd; r += 2) {
        const float vv = src[r * 128 + c];
        s1 += vv; s2 = fmaf(vv, vv, s2);
    }
    __shared__ float sh[2][2][128];
    sh[rh][0][c] = s1; sh[rh][1][c] = s2;
    __syncthreads();
    if (tid < 128) {
        g_ps[which][blockIdx.x][tid] = sh[0][0][tid] + sh[1][0][tid];
        g_pq[which][blockIdx.x][tid] = sh[0][1][tid] + sh[1][1][tid];
    }
}

__global__ void __launch_bounds__(128) bnfin_kernel(
    int which, const float* __restrict__ gamma, const float* __restrict__ beta)
{
    const int c = threadIdx.x;
    float s1 = 0.f, s2 = 0.f;
#pragma unroll
    for (int b = 0; b < 32; ++b) { s1 += g_ps[which][b][c]; s2 += g_pq[which][b][c]; }
    const float mu   = s1 * (1.f / BATCH);
    const float var  = s2 * (1.f / BATCH) - mu * mu;
    const float rstd = rsqrtf(var + 1e-5f);
    const float sc   = gamma[c] * rstd;
    if (which) { g_bns2[c] = sc; g_bnh2[c] = beta[c] - mu * sc; }
    else       { g_bns1[c] = sc; g_bnh1[c] = beta[c] - mu * sc; }
}

// =====================================================================
// Layer 2: y2 = leaky( BN1(y1) @ pw2.T + pb2 )   K=128
// 64 blocks of 32 rows x 128 cols; microtile 4x4; vector LDS.
// =====================================================================
__global__ void __launch_bounds__(256) gemm2_kernel(
    const float* __restrict__ W, const float* __restrict__ bias)
{
    __shared__ float xs[32][32];
    __shared__ float ws[32][128];
    const int rowBase = blockIdx.x * 32;
    const int tid = threadIdx.x;
    const int ty = tid >> 5, tx = tid & 31;

    float acc[4][4];
#pragma unroll
    for (int i = 0; i < 4; ++i)
#pragma unroll
        for (int j = 0; j < 4; ++j) acc[i][j] = 0.f;

    for (int kb = 0; kb < 128; kb += 32) {
        __syncthreads();
        if (tid < 256) {   // x tile: 32 rows x 32 k, BN affine on load
            const int idx = tid;
            const int row = idx & 31;
            const int k4  = (idx >> 5) * 4;
            const float4 vv = *reinterpret_cast<const float4*>(&g_y1[(rowBase + row) * 128 + kb + k4]);
            const float4 sc = *reinterpret_cast<const float4*>(&g_bns1[kb + k4]);
            const float4 sh = *reinterpret_cast<const float4*>(&g_bnh1[kb + k4]);
            xs[k4 + 0][row] = fmaf(vv.x, sc.x, sh.x);
            xs[k4 + 1][row] = fmaf(vv.y, sc.y, sh.y);
            xs[k4 + 2][row] = fmaf(vv.z, sc.z, sh.z);
            xs[k4 + 3][row] = fmaf(vv.w, sc.w, sh.w);
        }
        {
            const int col = tid >> 1;
            const int k0  = (tid & 1) * 16;
#pragma unroll
            for (int u = 0; u < 16; u += 4) {
                const float4 vv = *reinterpret_cast<const float4*>(&W[col * 128 + kb + k0 + u]);
                ws[k0 + u + 0][col] = vv.x; ws[k0 + u + 1][col] = vv.y;
                ws[k0 + u + 2][col] = vv.z; ws[k0 + u + 3][col] = vv.w;
            }
        }
        __syncthreads();
#pragma unroll
        for (int kk = 0; kk < 32; ++kk) {
            const float4 A = *reinterpret_cast<const float4*>(&xs[kk][ty * 4]);
            const float4 B = *reinterpret_cast<const float4*>(&ws[kk][tx * 4]);
            const float a[4] = {A.x, A.y, A.z, A.w};
            const float bb[4] = {B.x, B.y, B.z, B.w};
#pragma unroll
            for (int i = 0; i < 4; ++i)
#pragma unroll
                for (int j = 0; j < 4; ++j) acc[i][j] = fmaf(a[i], bb[j], acc[i][j]);
        }
    }
#pragma unroll
    for (int i = 0; i < 4; ++i) {
        const int row = rowBase + ty * 4 + i;
        const float4 bv = *reinterpret_cast<const float4*>(&bias[tx * 4]);
        float4 vv = make_float4(leaky(acc[i][0] + bv.x), leaky(acc[i][1] + bv.y),
                                leaky(acc[i][2] + bv.z), leaky(acc[i][3] + bv.w));
        *reinterpret_cast<float4*>(&g_y2[row * 128 + tx * 4]) = vv;
    }
}

// =====================================================================
// Layer 3: out = tanh( BN2(y2) @ pw3.T + pb3 )   K=128, N=64
// 64 blocks of 32 rows x 64 cols; microtile 2x4.
// =====================================================================
__global__ void __launch_bounds__(256) gemm3_kernel(
    const float* __restrict__ W, const float* __restrict__ bias, float* __restrict__ out)
{
    __shared__ float xs[32][32];
    __shared__ float ws[32][64];
    const int rowBase = blockIdx.x * 32;
    const int tid = threadIdx.x;
    const int ty = tid >> 4;        // 0..15, 2 rows each
    const int tx = tid & 15;        // 0..15, 4 cols each

    float acc[2][4];
#pragma unroll
    for (int i = 0; i < 2; ++i)
#pragma unroll
        for (int j = 0; j < 4; ++j) acc[i][j] = 0.f;

    for (int kb = 0; kb < 128; kb += 32) {
        __syncthreads();
        {   // x tile with BN affine
            const int row = tid & 31;
            const int k4  = (tid >> 5) * 4;
            const float4 vv = *reinterpret_cast<const float4*>(&g_y2[(rowBase + row) * 128 + kb + k4]);
            const float4 sc = *reinterpret_cast<const float4*>(&g_bns2[kb + k4]);
            const float4 sh = *reinterpret_cast<const float4*>(&g_bnh2[kb + k4]);
            xs[k4 + 0][row] = fmaf(vv.x, sc.x, sh.x);
            xs[k4 + 1][row] = fmaf(vv.y, sc.y, sh.y);
            xs[k4 + 2][row] = fmaf(vv.z, sc.z, sh.z);
            xs[k4 + 3][row] = fmaf(vv.w, sc.w, sh.w);
        }
        {   // w tile: 64 cols x 32 k = 2048 floats, 8 per thread
            const int col = tid >> 2;
            const int k0  = (tid & 3) * 8;
#pragma unroll
            for (int u = 0; u < 8; u += 4) {
                const float4 vv = *reinterpret_cast<const float4*>(&W[col * 128 + kb + k0 + u]);
                ws[k0 + u + 0][col] = vv.x; ws[k0 + u + 1][col] = vv.y;
                ws[k0 + u + 2][col] = vv.z; ws[k0 + u + 3][col] = vv.w;
            }
        }
        __syncthreads();
#pragma unroll
        for (int kk = 0; kk < 32; ++kk) {
            const float2 A = *reinterpret_cast<const float2*>(&xs[kk][ty * 2]);
            const float4 B = *reinterpret_cast<const float4*>(&ws[kk][tx * 4]);
            const float a[2] = {A.x, A.y};
            const float bb[4] = {B.x, B.y, B.z, B.w};
#pragma unroll
            for (int i = 0; i < 2; ++i)
#pragma unroll
                for (int j = 0; j < 4; ++j) acc[i][j] = fmaf(a[i], bb[j], acc[i][j]);
        }
    }
    const float4 bv = *reinterpret_cast<const float4*>(&bias[tx * 4]);
#pragma unroll
    for (int i = 0; i < 2; ++i) {
        const int row = rowBase + ty * 2 + i;
        float4 vv = make_float4(tanhf(acc[i][0] + bv.x), tanhf(acc[i][1] + bv.y),
                                tanhf(acc[i][2] + bv.z), tanhf(acc[i][3] + bv.w));
        *reinterpret_cast<float4*>(&out[row * 64 + tx * 4]) = vv;
    }
}

// =====================================================================
extern "C" void kernel_launch(void* const* d_in, const int* in_sizes, int n_in,
                              void* d_out, int out_size)
{
    const float* noise  = (const float*)d_in[0];
    const float* labels = (const float*)d_in[1];
    const float* qparams= (const float*)d_in[2];
    const float* ew1 = (const float*)d_in[3];  const float* eb1 = (const float*)d_in[4];
    const float* ew2 = (const float*)d_in[5];  const float* eb2 = (const float*)d_in[6];
    const float* ew3 = (const float*)d_in[7];  const float* eb3 = (const float*)d_in[8];
    const float* pw1 = (const float*)d_in[9];  const float* pb1 = (const float*)d_in[10];
    const float* g1  = (const float*)d_in[11]; const float* be1 = (const float*)d_in[12];
    const float* pw2 = (const float*)d_in[13]; const float* pb2 = (const float*)d_in[14];
    const float* g2  = (const float*)d_in[15]; const float* be2 = (const float*)d_in[16];
    const float* pw3 = (const float*)d_in[17]; const float* pb3 = (const float*)d_in[18];
    float* out = (float*)d_out;

    embed_kernel<<<257, 256>>>(labels, qparams, ew1, eb1, ew2, eb2, ew3, eb3);
    qsim_kernel<<<BATCH * NGEN / 8, 256>>>(noise);
    gemm1p_kernel<<<128, 256>>>(pw1);
    reduce1_kernel<<<256, 256>>>(labels, pw1, pb1);
    bnpart_kernel<<<32, 256>>>(0);
    bnfin_kernel<<<1, 128>>>(0, g1, be1);
    gemm2_kernel<<<64, 256>>>(pw2, pb2);
    bnpart_kernel<<<32, 256>>>(1);
    bnfin_kernel<<<1, 128>>>(1, g2, be2);
    gemm3_kernel<<<64, 256>>>(pw3, pb3, out);
}

// round 5
// speedup vs baseline: 1.4675x; 1.1056x over previous
#include <cuda_runtime.h>
#include <math.h>

#define BATCH 2048
#define NQ    10
#define NGEN  4
#define DEPTH 6
#define PATCH 256
#define QOUT  1024
#define NCLS  10

typedef unsigned long long u64;

// ---------------- scratch (device globals; no allocation) ----------------
__device__ __align__(256) float g_angles[BATCH * 2 * NQ];   // (B,20)
__device__ __align__(256) float g_qf[BATCH * QOUT];         // (B,1024)
__device__ __align__(256) float g_y1[BATCH * 128];
__device__ __align__(256) float g_y2[BATCH * 128];
__device__ __align__(16)  float g_wc[NGEN * DEPTH * NQ], g_ws[NGEN * DEPTH * NQ];
__device__ __align__(256) float g_ps[2][32][128];      // BN partial sums
__device__ __align__(256) float g_pq[2][32][128];      // BN partial sumsq
__device__ __align__(256) float g_p1[4][BATCH * 128];  // gemm1 split-K partials
__device__ __align__(256) float g_wtail[NCLS][128];    // pw1 label-tail, transposed

__device__ __forceinline__ float leaky(float x) { return x > 0.f ? x : 0.2f * x; }

// ---------------- packed f32x2 helpers ----------------
__device__ __forceinline__ u64 pk2(float lo, float hi) {
    u64 r; asm("mov.b64 %0,{%1,%2};" : "=l"(r) : "f"(lo), "f"(hi)); return r;
}
__device__ __forceinline__ void upk2(float& lo, float& hi, u64 v) {
    asm("mov.b64 {%0,%1},%2;" : "=f"(lo), "=f"(hi) : "l"(v));
}
__device__ __forceinline__ u64 f2fma(u64 a, u64 b, u64 c) {
    u64 d; asm("fma.rn.f32x2 %0,%1,%2,%3;" : "=l"(d) : "l"(a), "l"(b), "l"(c)); return d;
}
__device__ __forceinline__ u64 f2mul(u64 a, u64 b) {
    u64 d; asm("mul.rn.f32x2 %0,%1,%2;" : "=l"(d) : "l"(a), "l"(b)); return d;
}
__device__ __forceinline__ float2 cmul(float2 a, float2 b) {
    return make_float2(fmaf(a.x, b.x, -a.y * b.y), fmaf(a.x, b.y, a.y * b.x));
}

// =====================================================================
// Embedding MLP (blocks 0..255) + wtrig/wtail precompute (block 256).
// =====================================================================
__global__ void __launch_bounds__(256) embed_kernel(
    const float* __restrict__ lab, const float* __restrict__ qp,
    const float* __restrict__ pw1,
    const float* __restrict__ ew1, const float* __restrict__ eb1,
    const float* __restrict__ ew2, const float* __restrict__ eb2,
    const float* __restrict__ ew3, const float* __restrict__ eb3)
{
    if (blockIdx.x == 256) {
        const int i = threadIdx.x;
        if (i < NGEN * DEPTH * NQ) {
            float s, c; __sincosf(0.5f * qp[i], &s, &c);
            g_wc[i] = c; g_ws[i] = s;
        }
        if (i < 128) {
#pragma unroll
            for (int c = 0; c < NCLS; ++c)
                g_wtail[c][i] = pw1[i * 1034 + QOUT + c];
        }
        return;
    }
    const int wip  = threadIdx.x >> 5;
    const int row  = blockIdx.x * 8 + wip;
    const unsigned lane = threadIdx.x & 31u;
    __shared__ float h1s[8][32];
    __shared__ float h2s[8][64];

    float lv[NCLS];
    const float* L = lab + row * NCLS;
#pragma unroll
    for (int c = 0; c < NCLS; ++c) lv[c] = L[c];

    {
        float a = eb1[lane];
#pragma unroll
        for (int c = 0; c < NCLS; ++c) a = fmaf(lv[c], ew1[lane * NCLS + c], a);
        h1s[wip][lane] = leaky(a);
    }
    __syncwarp();
#pragma unroll
    for (int j = 0; j < 2; ++j) {
        const int o = lane + 32 * j;
        float a = eb2[o];
#pragma unroll
        for (int i = 0; i < 32; ++i) a = fmaf(h1s[wip][i], ew2[o * 32 + i], a);
        h2s[wip][o] = leaky(a);
    }
    __syncwarp();
    if (lane < 2 * NQ) {
        float a = eb3[lane];
#pragma unroll
        for (int i = 0; i < 64; ++i) a = fmaf(h2s[wip][i], ew3[lane * 64 + i], a);
        g_angles[row * 2 * NQ + lane] = tanhf(a) * 3.14159265358979323846f;
    }
}

// =====================================================================
// Quantum circuit: one warp per (batch, generator).
// Pre-variational state is a PRODUCT state computed in closed form:
//   per qubit (RY(nz)·RY(an) then RZ(az)):
//     f(0) = cos θ · (cos φ, -sin φ),  f(1) = sin θ · (cos φ, sin φ)
//   with θ = (nz+an)/2, φ = az/2.  amp(i) = Π_q f_q(bit_{9-q}(i)).
// State layout: i = r*32+lane; qubit q <-> bit 9-q (q<=4 reg, q>=5 lane).
// =====================================================================

// per-qubit factor pair
__device__ __forceinline__ void qfac(float th, float ph, float2& f0, float2& f1)
{
    float ct, st, cp, sp;
    __sincosf(th, &st, &ct);
    __sincosf(ph, &sp, &cp);
    f0 = make_float2(ct * cp, -ct * sp);
    f1 = make_float2(st * cp,  st * sp);
}

template <int B>
__device__ __forceinline__ void ry_p(u64 (&v)[32], u64 c2, u64 s2, u64 ns2, unsigned lane)
{
    if (B >= 5) {
        const int m = 1 << (B - 5);
#pragma unroll
        for (int r = 0; r < 32; ++r) {
            if (!(r & m)) {
                const u64 a0 = v[r], a1 = v[r | m];
                v[r]     = f2fma(ns2, a1, f2mul(c2, a0));
                v[r | m] = f2fma(s2,  a0, f2mul(c2, a1));
            }
        }
    } else {
        const unsigned mk = 1u << B;
        const u64 t2 = (lane & mk) ? s2 : ns2;
#pragma unroll
        for (int r = 0; r < 32; ++r) {
            const u64 p = __shfl_xor_sync(0xffffffffu, v[r], mk);
            v[r] = f2fma(t2, p, f2mul(c2, v[r]));
        }
    }
}

__global__ void __launch_bounds__(256, 2) qsim_kernel(const float* __restrict__ noise)
{
    const int w = (blockIdx.x * 256 + threadIdx.x) >> 5;
    const unsigned lane = threadIdx.x & 31u;
    const int b = w >> 2, g = w & 3;
    const float* nz = noise + b * NQ;
    const float* an = g_angles + b * 2 * NQ;
    const float* az = an + NQ;

    // --- closed-form product state ---
    // lane qubits q=5..9 <-> lane bit 9-q (4..0): fold into scalar L
    float2 Lf;
    {
        float2 f0, f1;
        qfac(0.5f * (nz[5] + an[5]), 0.5f * az[5], f0, f1);      // lane bit 4
        Lf = ((lane >> 4) & 1u) ? f1 : f0;
#pragma unroll
        for (int q = 6; q <= 9; ++q) {
            qfac(0.5f * (nz[q] + an[q]), 0.5f * az[q], f0, f1);  // lane bit 9-q
            Lf = cmul(Lf, ((lane >> (9 - q)) & 1u) ? f1 : f0);
        }
    }
    // reg qubits: q=0 <-> reg bit 4, q=1 <-> bit 3 | q=2,3,4 <-> bits 2,1,0
    float2 Lh[4];   // L * f_q0[bit4] * f_q1[bit3]
    {
        float2 f0, f1, e0, e1;
        qfac(0.5f * (nz[0] + an[0]), 0.5f * az[0], f0, f1);
        qfac(0.5f * (nz[1] + an[1]), 0.5f * az[1], e0, e1);
        const float2 La = cmul(Lf, f0), Lb = cmul(Lf, f1);
        Lh[0] = cmul(La, e0); Lh[1] = cmul(La, e1);
        Lh[2] = cmul(Lb, e0); Lh[3] = cmul(Lb, e1);
    }
    float2 Rlo[8];  // f_q2[bit2] * f_q3[bit1] * f_q4[bit0]
    {
        float2 f0, f1, e0, e1, d0, d1;
        qfac(0.5f * (nz[2] + an[2]), 0.5f * az[2], f0, f1);
        qfac(0.5f * (nz[3] + an[3]), 0.5f * az[3], e0, e1);
        qfac(0.5f * (nz[4] + an[4]), 0.5f * az[4], d0, d1);
        const float2 t0 = cmul(f0, e0), t1 = cmul(f0, e1),
                     t2 = cmul(f1, e0), t3 = cmul(f1, e1);
        Rlo[0] = cmul(t0, d0); Rlo[1] = cmul(t0, d1);
        Rlo[2] = cmul(t1, d0); Rlo[3] = cmul(t1, d1);
        Rlo[4] = cmul(t2, d0); Rlo[5] = cmul(t2, d1);
        Rlo[6] = cmul(t3, d0); Rlo[7] = cmul(t3, d1);
    }
    u64 v[32];
#pragma unroll
    for (int r = 0; r < 32; ++r) {
        const float2 a = cmul(Lh[r >> 3], Rlo[r & 7]);
        v[r] = pk2(a.x, a.y);
    }

    // CZ chain sign decomposition
    const bool pA = (__popc(lane & (lane >> 1)) & 1) != 0;
    const bool pB = pA ^ (((lane >> 4) & 1u) != 0);
    const float fA = pA ? -1.f : 1.f, fB = pB ? -1.f : 1.f;
    const u64 uA  = pk2(fA, fA),   uB  = pk2(fB, fB);
    const u64 uAn = pk2(-fA, -fA), uBn = pk2(-fB, -fB);

    const float* wc  = g_wc + g * DEPTH * NQ;
    const float* wsn = g_ws + g * DEPTH * NQ;

    // --- 6 variational layers ---
#pragma unroll 1
    for (int l = 0; l < DEPTH; ++l) {
        const float* lc = wc + l * NQ;
        const float* ls = wsn + l * NQ;
#define RYW(q) { const float cc = lc[q], ss = ls[q]; \
                 ry_p<9 - (q)>(v, pk2(cc, cc), pk2(ss, ss), pk2(-ss, -ss), lane); }
        RYW(0) RYW(1) RYW(2) RYW(3) RYW(4) RYW(5) RYW(6) RYW(7) RYW(8) RYW(9)
#undef RYW
#pragma unroll
        for (int r = 0; r < 32; ++r) {
            const bool srg = ((__popc(r & (r >> 1)) & 1) != 0);
            const u64 f = (r & 1) ? (srg ? uBn : uB) : (srg ? uAn : uA);
            v[r] = f2mul(v[r], f);
        }
    }

    // --- output: probs of first 256 amps, / max ---
    float p[8];
    float mx = 0.f;
#pragma unroll
    for (int r = 0; r < 8; ++r) {
        const u64 sq = f2mul(v[r], v[r]);
        float x, y; upk2(x, y, sq);
        p[r] = x + y;
        mx = fmaxf(mx, p[r]);
    }
#pragma unroll
    for (int o = 16; o; o >>= 1) mx = fmaxf(mx, __shfl_xor_sync(0xffffffffu, mx, o));
    const float inv = 1.0f / mx;
    float* dst = g_qf + b * QOUT + g * PATCH;
#pragma unroll
    for (int r = 0; r < 8; ++r) dst[r * 32 + lane] = p[r] * inv;
}

// =====================================================================
// gemm1 split-K partial: 128 blocks = 32 row-tiles x 4 k-chunks.
// =====================================================================
__global__ void __launch_bounds__(256) gemm1p_kernel(const float* __restrict__ W)
{
    __shared__ float xs[32][64];
    __shared__ float ws[32][128];
    const int rowBase = (blockIdx.x >> 2) * 64;
    const int kc      = (blockIdx.x & 3) * 256;
    const int tid = threadIdx.x;
    const int ty = tid >> 5, tx = tid & 31;

    float acc[8][4];
#pragma unroll
    for (int i = 0; i < 8; ++i)
#pragma unroll
        for (int j = 0; j < 4; ++j) acc[i][j] = 0.f;

    for (int kb = 0; kb < 256; kb += 32) {
        __syncthreads();
#pragma unroll
        for (int t = 0; t < 2; ++t) {
            const int idx = tid + t * 256;
            const int row = idx & 63;
            const int k4  = (idx >> 6) * 4;
            const float4 vv = *reinterpret_cast<const float4*>(
                &g_qf[(rowBase + row) * QOUT + kc + kb + k4]);
            xs[k4 + 0][row] = vv.x; xs[k4 + 1][row] = vv.y;
            xs[k4 + 2][row] = vv.z; xs[k4 + 3][row] = vv.w;
        }
        {
            const int col = tid >> 1;
            const int k0  = (tid & 1) * 16;
#pragma unroll
            for (int u = 0; u < 16; u += 2) {
                const float2 vv = *reinterpret_cast<const float2*>(
                    &W[col * 1034 + kc + kb + k0 + u]);
                ws[k0 + u + 0][col] = vv.x;
                ws[k0 + u + 1][col] = vv.y;
            }
        }
        __syncthreads();
#pragma unroll
        for (int kk = 0; kk < 32; ++kk) {
            const float4 A0 = *reinterpret_cast<const float4*>(&xs[kk][ty * 8]);
            const float4 A1 = *reinterpret_cast<const float4*>(&xs[kk][ty * 8 + 4]);
            const float4 B  = *reinterpret_cast<const float4*>(&ws[kk][tx * 4]);
            const float a[8] = {A0.x, A0.y, A0.z, A0.w, A1.x, A1.y, A1.z, A1.w};
            const float bb[4] = {B.x, B.y, B.z, B.w};
#pragma unroll
            for (int i = 0; i < 8; ++i)
#pragma unroll
                for (int j = 0; j < 4; ++j) acc[i][j] = fmaf(a[i], bb[j], acc[i][j]);
        }
    }

    float* dst = g_p1[blockIdx.x & 3];
#pragma unroll
    for (int i = 0; i < 8; ++i) {
        const int row = rowBase + ty * 8 + i;
        float4 vv = make_float4(acc[i][0], acc[i][1], acc[i][2], acc[i][3]);
        *reinterpret_cast<float4*>(&dst[row * 128 + tx * 4]) = vv;
    }
}

// reduce partials + bias + label tail (coalesced via g_wtail) + leaky -> y1
__global__ void __launch_bounds__(256) reduce1_kernel(
    const float* __restrict__ lab, const float* __restrict__ bias)
{
    const int t = blockIdx.x * 256 + threadIdx.x;
    const int row = t >> 5;
    const int cg  = (t & 31) * 4;
    float4 s = *reinterpret_cast<const float4*>(&g_p1[0][row * 128 + cg]);
    const float4 s1 = *reinterpret_cast<const float4*>(&g_p1[1][row * 128 + cg]);
    const float4 s2 = *reinterpret_cast<const float4*>(&g_p1[2][row * 128 + cg]);
    const float4 s3 = *reinterpret_cast<const float4*>(&g_p1[3][row * 128 + cg]);
    s.x += s1.x + s2.x + s3.x;  s.y += s1.y + s2.y + s3.y;
    s.z += s1.z + s2.z + s3.z;  s.w += s1.w + s2.w + s3.w;
    const float4 bv = *reinterpret_cast<const float4*>(&bias[cg]);
    s.x += bv.x; s.y += bv.y; s.z += bv.z; s.w += bv.w;
#pragma unroll
    for (int c = 0; c < NCLS; ++c) {
        const float lv = lab[row * NCLS + c];                     // warp-broadcast
        const float4 wv = *reinterpret_cast<const float4*>(&g_wtail[c][cg]);
        s.x = fmaf(lv, wv.x, s.x); s.y = fmaf(lv, wv.y, s.y);
        s.z = fmaf(lv, wv.z, s.z); s.w = fmaf(lv, wv.w, s.w);
    }
    s.x = leaky(s.x); s.y = leaky(s.y); s.z = leaky(s.z); s.w = leaky(s.w);
    *reinterpret_cast<float4*>(&g_y1[row * 128 + cg]) = s;
}

// =====================================================================
// BN partials (two-stage, coalesced); finalize fused into gemm2/gemm3.
// =====================================================================
__global__ void __launch_bounds__(256) bnpart_kernel(int which)
{
    const float* src = which ? g_y2 : g_y1;
    const int tid = threadIdx.x;
    const int c = tid & 127, rh = tid >> 7;
    float s1 = 0.f, s2 = 0.f;
    const int rEnd = blockIdx.x * 64 + 64;
    for (int r = blockIdx.x * 64 + rh; r < rEnd; r += 2) {
        const float vv = src[r * 128 + c];
        s1 += vv; s2 = fmaf(vv, vv, s2);
    }
    __shared__ float sh[2][2][128];
    sh[rh][0][c] = s1; sh[rh][1][c] = s2;
    __syncthreads();
    if (tid < 128) {
        g_ps[which][blockIdx.x][tid] = sh[0][0][tid] + sh[1][0][tid];
        g_pq[which][blockIdx.x][tid] = sh[0][1][tid] + sh[1][1][tid];
    }
}

// compute BN affine (scale, shift) for column c from partials
__device__ __forceinline__ void bn_affine(
    int which, int c, const float* gamma, const float* beta, float& sc, float& sh)
{
    float s1 = 0.f, s2 = 0.f;
#pragma unroll
    for (int b = 0; b < 32; ++b) { s1 += g_ps[which][b][c]; s2 += g_pq[which][b][c]; }
    const float mu   = s1 * (1.f / BATCH);
    const float var  = s2 * (1.f / BATCH) - mu * mu;
    const float rstd = rsqrtf(var + 1e-5f);
    sc = gamma[c] * rstd;
    sh = beta[c] - mu * sc;
}

// =====================================================================
// Layer 2: y2 = leaky( BN1(y1) @ pw2.T + pb2 )   K=128 (BN finalize fused)
// =====================================================================
__global__ void __launch_bounds__(256) gemm2_kernel(
    const float* __restrict__ W, const float* __restrict__ bias,
    const float* __restrict__ gamma, const float* __restrict__ beta)
{
    __shared__ float xs[32][32];
    __shared__ float ws[32][128];
    __shared__ float bns[128], bnh[128];
    const int rowBase = blockIdx.x * 32;
    const int tid = threadIdx.x;
    const int ty = tid >> 5, tx = tid & 31;

    if (tid < 128) {
        float sc, sh; bn_affine(0, tid, gamma, beta, sc, sh);
        bns[tid] = sc; bnh[tid] = sh;
    }
    __syncthreads();

    float acc[4][4];
#pragma unroll
    for (int i = 0; i < 4; ++i)
#pragma unroll
        for (int j = 0; j < 4; ++j) acc[i][j] = 0.f;

    for (int kb = 0; kb < 128; kb += 32) {
        __syncthreads();
        {
            const int row = tid & 31;
            const int k4  = (tid >> 5) * 4;
            const float4 vv = *reinterpret_cast<const float4*>(&g_y1[(rowBase + row) * 128 + kb + k4]);
            xs[k4 + 0][row] = fmaf(vv.x, bns[kb + k4 + 0], bnh[kb + k4 + 0]);
            xs[k4 + 1][row] = fmaf(vv.y, bns[kb + k4 + 1], bnh[kb + k4 + 1]);
            xs[k4 + 2][row] = fmaf(vv.z, bns[kb + k4 + 2], bnh[kb + k4 + 2]);
            xs[k4 + 3][row] = fmaf(vv.w, bns[kb + k4 + 3], bnh[kb + k4 + 3]);
        }
        {
            const int col = tid >> 1;
            const int k0  = (tid & 1) * 16;
#pragma unroll
            for (int u = 0; u < 16; u += 4) {
                const float4 vv = *reinterpret_cast<const float4*>(&W[col * 128 + kb + k0 + u]);
                ws[k0 + u + 0][col] = vv.x; ws[k0 + u + 1][col] = vv.y;
                ws[k0 + u + 2][col] = vv.z; ws[k0 + u + 3][col] = vv.w;
            }
        }
        __syncthreads();
#pragma unroll
        for (int kk = 0; kk < 32; ++kk) {
            const float4 A = *reinterpret_cast<const float4*>(&xs[kk][ty * 4]);
            const float4 B = *reinterpret_cast<const float4*>(&ws[kk][tx * 4]);
            const float a[4] = {A.x, A.y, A.z, A.w};
            const float bb[4] = {B.x, B.y, B.z, B.w};
#pragma unroll
            for (int i = 0; i < 4; ++i)
#pragma unroll
                for (int j = 0; j < 4; ++j) acc[i][j] = fmaf(a[i], bb[j], acc[i][j]);
        }
    }
    const float4 bv = *reinterpret_cast<const float4*>(&bias[tx * 4]);
#pragma unroll
    for (int i = 0; i < 4; ++i) {
        const int row = rowBase + ty * 4 + i;
        float4 vv = make_float4(leaky(acc[i][0] + bv.x), leaky(acc[i][1] + bv.y),
                                leaky(acc[i][2] + bv.z), leaky(acc[i][3] + bv.w));
        *reinterpret_cast<float4*>(&g_y2[row * 128 + tx * 4]) = vv;
    }
}

// =====================================================================
// Layer 3: out = tanh( BN2(y2) @ pw3.T + pb3 )   K=128, N=64 (BN fused)
// =====================================================================
__global__ void __launch_bounds__(256) gemm3_kernel(
    const float* __restrict__ W, const float* __restrict__ bias,
    const float* __restrict__ gamma, const float* __restrict__ beta,
    float* __restrict__ out)
{
    __shared__ float xs[32][32];
    __shared__ float ws[32][64];
    __shared__ float bns[128], bnh[128];
    const int rowBase = blockIdx.x * 32;
    const int tid = threadIdx.x;
    const int ty = tid >> 4;
    const int tx = tid & 15;

    if (tid < 128) {
        float sc, sh; bn_affine(1, tid, gamma, beta, sc, sh);
        bns[tid] = sc; bnh[tid] = sh;
    }
    __syncthreads();

    float acc[2][4];
#pragma unroll
    for (int i = 0; i < 2; ++i)
#pragma unroll
        for (int j = 0; j < 4; ++j) acc[i][j] = 0.f;

    for (int kb = 0; kb < 128; kb += 32) {
        __syncthreads();
        {
            const int row = tid & 31;
            const int k4  = (tid >> 5) * 4;
            const float4 vv = *reinterpret_cast<const float4*>(&g_y2[(rowBase + row) * 128 + kb + k4]);
            xs[k4 + 0][row] = fmaf(vv.x, bns[kb + k4 + 0], bnh[kb + k4 + 0]);
            xs[k4 + 1][row] = fmaf(vv.y, bns[kb + k4 + 1], bnh[kb + k4 + 1]);
            xs[k4 + 2][row] = fmaf(vv.z, bns[kb + k4 + 2], bnh[kb + k4 + 2]);
            xs[k4 + 3][row] = fmaf(vv.w, bns[kb + k4 + 3], bnh[kb + k4 + 3]);
        }
        {
            const int col = tid >> 2;
            const int k0  = (tid & 3) * 8;
#pragma unroll
            for (int u = 0; u < 8; u += 4) {
                const float4 vv = *reinterpret_cast<const float4*>(&W[col * 128 + kb + k0 + u]);
                ws[k0 + u + 0][col] = vv.x; ws[k0 + u + 1][col] = vv.y;
                ws[k0 + u + 2][col] = vv.z; ws[k0 + u + 3][col] = vv.w;
            }
        }
        __syncthreads();
#pragma unroll
        for (int kk = 0; kk < 32; ++kk) {
            const float2 A = *reinterpret_cast<const float2*>(&xs[kk][ty * 2]);
            const float4 B = *reinterpret_cast<const float4*>(&ws[kk][tx * 4]);
            const float a[2] = {A.x, A.y};
            const float bb[4] = {B.x, B.y, B.z, B.w};
#pragma unroll
            for (int i = 0; i < 2; ++i)
#pragma unroll
                for (int j = 0; j < 4; ++j) acc[i][j] = fmaf(a[i], bb[j], acc[i][j]);
        }
    }
    const float4 bv = *reinterpret_cast<const float4*>(&bias[tx * 4]);
#pragma unroll
    for (int i = 0; i < 2; ++i) {
        const int row = rowBase + ty * 2 + i;
        float4 vv = make_float4(tanhf(acc[i][0] + bv.x), tanhf(acc[i][1] + bv.y),
                                tanhf(acc[i][2] + bv.z), tanhf(acc[i][3] + bv.w));
        *reinterpret_cast<float4*>(&out[row * 64 + tx * 4]) = vv;
    }
}

// =====================================================================
extern "C" void kernel_launch(void* const* d_in, const int* in_sizes, int n_in,
                              void* d_out, int out_size)
{
    const float* noise  = (const float*)d_in[0];
    const float* labels = (const float*)d_in[1];
    const float* qparams= (const float*)d_in[2];
    const float* ew1 = (const float*)d_in[3];  const float* eb1 = (const float*)d_in[4];
    const float* ew2 = (const float*)d_in[5];  const float* eb2 = (const float*)d_in[6];
    const float* ew3 = (const float*)d_in[7];  const float* eb3 = (const float*)d_in[8];
    const float* pw1 = (const float*)d_in[9];  const float* pb1 = (const float*)d_in[10];
    const float* g1  = (const float*)d_in[11]; const float* be1 = (const float*)d_in[12];
    const float* pw2 = (const float*)d_in[13]; const float* pb2 = (const float*)d_in[14];
    const float* g2  = (const float*)d_in[15]; const float* be2 = (const float*)d_in[16];
    const float* pw3 = (const float*)d_in[17]; const float* pb3 = (const float*)d_in[18];
    float* out = (float*)d_out;

    embed_kernel<<<257, 256>>>(labels, qparams, pw1, ew1, eb1, ew2, eb2, ew3, eb3);
    qsim_kernel<<<BATCH * NGEN / 8, 256>>>(noise);
    gemm1p_kernel<<<128, 256>>>(pw1);
    reduce1_kernel<<<256, 256>>>(labels, pb1);
    bnpart_kernel<<<32, 256>>>(0);
    gemm2_kernel<<<64, 256>>>(pw2, pb2, g1, be1);
    bnpart_kernel<<<32, 256>>>(1);
    gemm3_kernel<<<64, 256>>>(pw3, pb3, g2, be2, out);
}